// round 15
// baseline (speedup 1.0000x reference)
#include <cuda_runtime.h>
#include <cuda_bf16.h>
#include <cstdint>

// Problem dims: B=1, S=256, N=512, C_M=64, C_Z=128, H=8, C_H=32  (H*C_H = 256)
//
// Pipeline (tf32 tensor-core GEMMs):
//   k_ln_m  : LN(m) -> d_mn (tf32-rounded)            [r=s*512+n][64]
//   k_mproj : tf32 MMA: d_mn @ [Wm;Wg]^T              -> d_V [h][t][j] (transposed), d_G [r][256]
//   k_zsm   : FUSED LN(z).Wz + mask bias + softmax    -> d_W [h][i*512+j] (tf32-rounded)
//   k_gemm  : tf32 MMA, 2 CTAs/SM + cp.async          -> d_O [i][s][h*32+e]   (slot 4 -> profiled)
//   k_out   : tf32 MMA: (G .* O) @ Wo^T               -> out [s][i][64]

// ---------------- scratch ----------------
__device__ float d_mn[131072 * 64];
__device__ float d_V [8 * 8192 * 512];       // [h][t=s*32+e][j]  tf32-rounded
__device__ float d_G [131072 * 256];
__device__ float d_W [8 * 512 * 512];        // tf32-rounded softmax weights
__device__ float d_O [512 * 256 * 256];

__inline__ __device__ float warpSum(float v) {
    #pragma unroll
    for (int o = 16; o > 0; o >>= 1) v += __shfl_xor_sync(0xffffffffu, v, o);
    return v;
}
__inline__ __device__ float warpMax(float v) {
    #pragma unroll
    for (int o = 16; o > 0; o >>= 1) v = fmaxf(v, __shfl_xor_sync(0xffffffffu, v, o));
    return v;
}
__inline__ __device__ float to_tf32(float x) {
    uint32_t u;
    asm("cvt.rna.tf32.f32 %0, %1;" : "=r"(u) : "f"(x));
    return __uint_as_float(u);
}
#define MMA_TF32(acc, af, bf)                                             \
    asm volatile(                                                         \
        "mma.sync.aligned.m16n8k8.row.col.f32.tf32.tf32.f32 "             \
        "{%0,%1,%2,%3}, {%4,%5,%6,%7}, {%8,%9}, {%0,%1,%2,%3};\n"         \
        : "+f"((acc)[0]), "+f"((acc)[1]), "+f"((acc)[2]), "+f"((acc)[3])  \
        : "r"((af)[0]), "r"((af)[1]), "r"((af)[2]), "r"((af)[3]),         \
          "r"((bf)[0]), "r"((bf)[1]))
#define CP_ASYNC16(smem_u32, gptr)                                        \
    asm volatile("cp.async.cg.shared.global [%0], [%1], 16;\n"            \
                 :: "r"(smem_u32), "l"(gptr))

// ---------------- kernel 1: LayerNorm(m), tf32-rounded ----------------
__global__ void k_ln_m(const float* __restrict__ m,
                       const float* __restrict__ lw, const float* __restrict__ lb)
{
    int tid = threadIdx.x, warp = tid >> 5, lane = tid & 31;
    int r = blockIdx.x * 8 + warp;
    const float* row = m + (size_t)r * 64;
    float x0 = row[lane];
    float x1 = row[lane + 32];
    float s  = warpSum(x0 + x1);
    float ss = warpSum(x0 * x0 + x1 * x1);
    float mu  = s * (1.0f / 64.0f);
    float var = ss * (1.0f / 64.0f) - mu * mu;
    float rinv = rsqrtf(var + 1e-5f);
    d_mn[(size_t)r * 64 + lane]      = to_tf32((x0 - mu) * rinv * lw[lane]      + lb[lane]);
    d_mn[(size_t)r * 64 + lane + 32] = to_tf32((x1 - mu) * rinv * lw[lane + 32] + lb[lane + 32]);
}

// ---------------- kernel 2: V / G projection — tf32 MMA ----------------
__global__ void __launch_bounds__(256) k_mproj(const float* __restrict__ Wm,
                                               const float* __restrict__ Wg)
{
    __shared__ float As[128][36];
    __shared__ float Bs[32][136];
    int tid = threadIdx.x;
    int warp = tid >> 5, lane = tid & 31;
    int gid = lane >> 2, tig = lane & 3;
    int warp_m = warp & 1, warp_n = warp >> 1;
    int bx = blockIdx.x, by = blockIdx.y;
    bool isV = (bx < 2);

    float acc[4][4][4] = {};
    for (int kt = 0; kt < 64; kt += 32) {
        #pragma unroll
        for (int l = 0; l < 4; l++) {
            int e = tid + l * 256;
            int ar = e >> 3, ac = (e & 7) * 4;
            *(float4*)(&As[ar][ac]) =
                *(const float4*)(d_mn + (size_t)(by * 128 + ar) * 64 + kt + ac);
        }
        {
            int o_local = tid >> 1;
            int k0 = (tid & 1) * 16;
            int o_global = bx * 128 + o_local;
            const float* Wrow = isV ? (Wm + (size_t)o_global * 64)
                                    : (Wg + (size_t)(o_global - 256) * 64);
            #pragma unroll
            for (int i = 0; i < 16; i++) Bs[k0 + i][o_local] = to_tf32(Wrow[kt + k0 + i]);
        }
        __syncthreads();
        #pragma unroll
        for (int k0 = 0; k0 < 32; k0 += 8) {
            uint32_t af[4][4], bf[4][2];
            #pragma unroll
            for (int mt = 0; mt < 4; mt++) {
                int r0 = warp_m * 64 + mt * 16 + gid;
                af[mt][0] = __float_as_uint(As[r0    ][k0 + tig]);
                af[mt][1] = __float_as_uint(As[r0 + 8][k0 + tig]);
                af[mt][2] = __float_as_uint(As[r0    ][k0 + tig + 4]);
                af[mt][3] = __float_as_uint(As[r0 + 8][k0 + tig + 4]);
            }
            #pragma unroll
            for (int nt = 0; nt < 4; nt++) {
                int c = warp_n * 32 + nt * 8 + gid;
                bf[nt][0] = __float_as_uint(Bs[k0 + tig    ][c]);
                bf[nt][1] = __float_as_uint(Bs[k0 + tig + 4][c]);
            }
            #pragma unroll
            for (int mt = 0; mt < 4; mt++)
                #pragma unroll
                for (int nt = 0; nt < 4; nt++)
                    MMA_TF32(acc[mt][nt], af[mt], bf[nt]);
        }
        __syncthreads();
    }

    #pragma unroll
    for (int mt = 0; mt < 4; mt++) {
        int rA = by * 128 + warp_m * 64 + mt * 16 + gid;
        #pragma unroll
        for (int nt = 0; nt < 4; nt++) {
            int o = bx * 128 + warp_n * 32 + nt * 8 + 2 * tig;
            #pragma unroll
            for (int half = 0; half < 2; half++) {
                int r = rA + half * 8;
                int s = r >> 9, n = r & 511;
                float c0 = acc[mt][nt][2 * half], c1 = acc[mt][nt][2 * half + 1];
                if (isV) {
                    int h = o >> 5, e = o & 31;
                    size_t t = (size_t)s * 32 + e;
                    d_V[((size_t)h * 8192 + t    ) * 512 + n] = to_tf32(c0);
                    d_V[((size_t)h * 8192 + t + 1) * 512 + n] = to_tf32(c1);
                } else {
                    size_t base = (size_t)r * 256 + (o - 256);
                    *(float2*)(d_G + base) =
                        make_float2(1.0f / (1.0f + expf(-c0)), 1.0f / (1.0f + expf(-c1)));
                }
            }
        }
    }
}

// ---------------- kernel 3: FUSED z path + softmax ----------------
// One block per i. Phase 1: 8 warps stride over j, each computing LN(z[i,j,:])
// and the 8 head logits into smem. Phase 2: warp h softmaxes head h's 512 logits
// and writes tf32-rounded weights.
__global__ void __launch_bounds__(256) k_zsm(const float* __restrict__ z,
                                             const float* __restrict__ mask,
                                             const float* __restrict__ lw,
                                             const float* __restrict__ lb,
                                             const float* __restrict__ Wz)
{
    __shared__ float sWz[8][128];
    __shared__ float sLw[128], sLb[128];
    __shared__ float sL[8][512];
    int tid = threadIdx.x;
    for (int q = tid; q < 1024; q += 256) sWz[q >> 7][q & 127] = Wz[q];
    if (tid < 128) { sLw[tid] = lw[tid]; sLb[tid] = lb[tid]; }
    __syncthreads();

    int warp = tid >> 5, lane = tid & 31;
    int i = blockIdx.x;

    for (int j = warp; j < 512; j += 8) {
        size_t r = (size_t)i * 512 + j;
        const float4 zx = *(const float4*)(z + r * 128 + lane * 4);
        float s  = zx.x + zx.y + zx.z + zx.w;
        float ss = zx.x*zx.x + zx.y*zx.y + zx.z*zx.z + zx.w*zx.w;
        s = warpSum(s); ss = warpSum(ss);
        float mu  = s * (1.0f / 128.0f);
        float var = ss * (1.0f / 128.0f) - mu * mu;
        float rinv = rsqrtf(var + 1e-5f);

        float4 w4 = *(const float4*)(sLw + lane * 4);
        float4 b4 = *(const float4*)(sLb + lane * 4);
        float y0 = (zx.x - mu) * rinv * w4.x + b4.x;
        float y1 = (zx.y - mu) * rinv * w4.y + b4.y;
        float y2 = (zx.z - mu) * rinv * w4.z + b4.z;
        float y3 = (zx.w - mu) * rinv * w4.w + b4.w;

        float bias = (1.0f - mask[r]) * (-1000000.0f);
        #pragma unroll
        for (int h = 0; h < 8; h++) {
            float4 wz = *(const float4*)(&sWz[h][lane * 4]);
            float p = y0*wz.x + y1*wz.y + y2*wz.z + y3*wz.w;
            p = warpSum(p);
            if (lane == 0) sL[h][j] = p + bias;
        }
    }
    __syncthreads();

    // phase 2: warp h -> softmax over sL[h][0..511]
    {
        int h = warp;
        float v[16];
        float mx = -1e30f;
        #pragma unroll
        for (int u = 0; u < 16; u++) { v[u] = sL[h][u * 32 + lane]; mx = fmaxf(mx, v[u]); }
        mx = warpMax(mx);
        float s = 0.f;
        #pragma unroll
        for (int u = 0; u < 16; u++) { v[u] = expf(v[u] - mx); s += v[u]; }
        s = warpSum(s);
        float inv = 1.0f / s;
        float* dst = d_W + (size_t)h * 262144 + (size_t)i * 512;
        #pragma unroll
        for (int u = 0; u < 16; u++) dst[u * 32 + lane] = to_tf32(v[u] * inv);
    }
}

// ---------------- kernel 4: big GEMM — tf32 MMA, 2 CTAs/SM + cp.async ----------------
// C[i, t] = sum_j w[h][i][j] * V[t][j].  A = d_W[h] [i][j]; B = d_V[h] [t][j].
// Single-buffered 36.9 KB smem; overlap comes from 2 resident CTAs per SM
// (while one waits at a barrier the other issues MMAs).
__global__ void __launch_bounds__(256, 2) k_gemm()
{
    __shared__ float As[128 * 36];
    __shared__ float Bs[128 * 36];
    int tid = threadIdx.x;
    int warp = tid >> 5, lane = tid & 31;
    int gid = lane >> 2, tig = lane & 3;
    int warp_m = warp & 1, warp_n = warp >> 1;
    int bx = blockIdx.x, by = blockIdx.y, h = blockIdx.z;
    const float* A  = d_W + (size_t)h * 262144;    // [i][j]
    const float* Bv = d_V + (size_t)h * 4194304;   // [t][j]
    uint32_t sA = (uint32_t)__cvta_generic_to_shared(As);
    uint32_t sB = (uint32_t)__cvta_generic_to_shared(Bs);

    float acc[4][4][4] = {};

    for (int kt = 0; kt < 512; kt += 32) {
        #pragma unroll
        for (int l = 0; l < 4; l++) {
            int e = tid + l * 256;
            int row = e >> 3, kc = (e & 7) * 4;
            CP_ASYNC16(sA + (row * 36 + kc) * 4,
                       A  + (size_t)(by * 128 + row) * 512 + kt + kc);
            CP_ASYNC16(sB + (row * 36 + kc) * 4,
                       Bv + (size_t)(bx * 128 + row) * 512 + kt + kc);
        }
        asm volatile("cp.async.commit_group;\n");
        asm volatile("cp.async.wait_group 0;\n" ::: "memory");
        __syncthreads();

        #pragma unroll
        for (int k0 = 0; k0 < 32; k0 += 8) {
            uint32_t af[4][4], bf[4][2];
            #pragma unroll
            for (int mt = 0; mt < 4; mt++) {
                int r0 = warp_m * 64 + mt * 16 + gid;
                af[mt][0] = __float_as_uint(As[ r0      * 36 + k0 + tig]);
                af[mt][1] = __float_as_uint(As[(r0 + 8) * 36 + k0 + tig]);
                af[mt][2] = __float_as_uint(As[ r0      * 36 + k0 + tig + 4]);
                af[mt][3] = __float_as_uint(As[(r0 + 8) * 36 + k0 + tig + 4]);
            }
            #pragma unroll
            for (int nt = 0; nt < 4; nt++) {
                int c = warp_n * 32 + nt * 8 + gid;
                bf[nt][0] = __float_as_uint(Bs[c * 36 + k0 + tig]);
                bf[nt][1] = __float_as_uint(Bs[c * 36 + k0 + tig + 4]);
            }
            #pragma unroll
            for (int mt = 0; mt < 4; mt++)
                #pragma unroll
                for (int nt = 0; nt < 4; nt++)
                    MMA_TF32(acc[mt][nt], af[mt], bf[nt]);
        }
        __syncthreads();
    }

    #pragma unroll
    for (int mt = 0; mt < 4; mt++) {
        int r0 = by * 128 + warp_m * 64 + mt * 16 + gid;
        #pragma unroll
        for (int nt = 0; nt < 4; nt++) {
            int t = bx * 128 + warp_n * 32 + nt * 8 + 2 * tig;
            int s = t >> 5, e = t & 31;
            size_t b0 = (size_t)r0 * 65536 + (size_t)s * 256 + h * 32 + e;
            size_t b1 = (size_t)(r0 + 8) * 65536 + (size_t)s * 256 + h * 32 + e;
            *(float2*)(d_O + b0) = make_float2(acc[mt][nt][0], acc[mt][nt][1]);
            *(float2*)(d_O + b1) = make_float2(acc[mt][nt][2], acc[mt][nt][3]);
        }
    }
}

// ---------------- kernel 5: gate + output projection — tf32 MMA ----------------
__global__ void __launch_bounds__(256) k_out(float* __restrict__ out,
                                             const float* __restrict__ Wo)
{
    __shared__ float As[128][36];
    __shared__ float Bs[32][72];
    int tid = threadIdx.x;
    int warp = tid >> 5, lane = tid & 31;
    int gid = lane >> 2, tig = lane & 3;
    int warp_m = warp >> 1, warp_n = warp & 1;
    int by = blockIdx.x;

    float acc[2][4][4] = {};
    for (int kt = 0; kt < 256; kt += 32) {
        #pragma unroll
        for (int l = 0; l < 4; l++) {
            int e = tid + l * 256;
            int ar = e >> 3, ac = (e & 7) * 4;
            int r = by * 128 + ar;
            int s = r >> 9, i = r & 511;
            float4 g4 = *(const float4*)(d_G + (size_t)r * 256 + kt + ac);
            float4 o4 = *(const float4*)(d_O + (size_t)i * 65536 + (size_t)s * 256 + kt + ac);
            As[ar][ac]   = to_tf32(g4.x * o4.x);
            As[ar][ac+1] = to_tf32(g4.y * o4.y);
            As[ar][ac+2] = to_tf32(g4.z * o4.z);
            As[ar][ac+3] = to_tf32(g4.w * o4.w);
        }
        {
            int cm = tid >> 2, k0 = (tid & 3) * 8;
            const float* Wrow = Wo + (size_t)cm * 256 + kt + k0;
            #pragma unroll
            for (int i = 0; i < 8; i++) Bs[k0 + i][cm] = to_tf32(Wrow[i]);
        }
        __syncthreads();
        #pragma unroll
        for (int k0 = 0; k0 < 32; k0 += 8) {
            uint32_t af[2][4], bf[4][2];
            #pragma unroll
            for (int mt = 0; mt < 2; mt++) {
                int r0 = warp_m * 32 + mt * 16 + gid;
                af[mt][0] = __float_as_uint(As[r0    ][k0 + tig]);
                af[mt][1] = __float_as_uint(As[r0 + 8][k0 + tig]);
                af[mt][2] = __float_as_uint(As[r0    ][k0 + tig + 4]);
                af[mt][3] = __float_as_uint(As[r0 + 8][k0 + tig + 4]);
            }
            #pragma unroll
            for (int nt = 0; nt < 4; nt++) {
                int c = warp_n * 32 + nt * 8 + gid;
                bf[nt][0] = __float_as_uint(Bs[k0 + tig    ][c]);
                bf[nt][1] = __float_as_uint(Bs[k0 + tig + 4][c]);
            }
            #pragma unroll
            for (int mt = 0; mt < 2; mt++)
                #pragma unroll
                for (int nt = 0; nt < 4; nt++)
                    MMA_TF32(acc[mt][nt], af[mt], bf[nt]);
        }
        __syncthreads();
    }

    #pragma unroll
    for (int mt = 0; mt < 2; mt++) {
        int r0 = by * 128 + warp_m * 32 + mt * 16 + gid;
        #pragma unroll
        for (int nt = 0; nt < 4; nt++) {
            int c = warp_n * 32 + nt * 8 + 2 * tig;
            *(float2*)(out + (size_t)r0 * 64 + c) =
                make_float2(acc[mt][nt][0], acc[mt][nt][1]);
            *(float2*)(out + (size_t)(r0 + 8) * 64 + c) =
                make_float2(acc[mt][nt][2], acc[mt][nt][3]);
        }
    }
}

extern "C" void kernel_launch(void* const* d_in, const int* in_sizes, int n_in,
                              void* d_out, int out_size)
{
    const float *m, *z, *mask, *lmw, *lmb, *lzw, *lzb, *Wm, *Wg, *Wz, *Wo;
    if (n_in > 0 && in_sizes[0] == 8388608) {           // insertion order
        m   = (const float*)d_in[0];  z   = (const float*)d_in[1];
        mask= (const float*)d_in[2];
        lmw = (const float*)d_in[3];  lmb = (const float*)d_in[4];
        lzw = (const float*)d_in[5];  lzb = (const float*)d_in[6];
        Wm  = (const float*)d_in[7];  Wg  = (const float*)d_in[8];
        Wz  = (const float*)d_in[9];  Wo  = (const float*)d_in[10];
    } else {                                            // alphabetical order
        Wg  = (const float*)d_in[0];  Wm  = (const float*)d_in[1];
        Wo  = (const float*)d_in[2];  Wz  = (const float*)d_in[3];
        lmb = (const float*)d_in[4];  lmw = (const float*)d_in[5];
        lzb = (const float*)d_in[6];  lzw = (const float*)d_in[7];
        m   = (const float*)d_in[8];  mask= (const float*)d_in[9];
        z   = (const float*)d_in[10];
    }
    float* out = (float*)d_out;

    k_ln_m<<<16384, 256>>>(m, lmw, lmb);                 // slot 1
    dim3 gp(4, 1024);
    k_mproj<<<gp, 256>>>(Wm, Wg);                        // slot 2
    k_zsm<<<512, 256>>>(z, mask, lzw, lzb, Wz);          // slot 3 (fused zpath+softmax)
    dim3 gg(64, 4, 8);
    k_gemm<<<gg, 256>>>();                               // slot 4 -> gets profiled
    k_out<<<1024, 256>>>(out, Wo);                       // slot 5
}

// round 16
// speedup vs baseline: 1.0581x; 1.0581x over previous
#include <cuda_runtime.h>
#include <cuda_bf16.h>
#include <cstdint>

// Problem dims: B=1, S=256, N=512, C_M=64, C_Z=128, H=8, C_H=32  (H*C_H = 256)
//
// Pipeline (tf32 tensor-core GEMMs):
//   k_ln_m    : LN(m) -> d_mn (tf32-rounded)        [r=s*512+n][64]
//   k_mproj   : tf32 MMA: d_mn @ [Wm;Wg]^T          -> d_V [h][t][j] (transposed), d_G [r][256]
//   k_zpath   : LN(z) . Wz[h] + mask bias           -> d_W logits
//   k_softmax : row softmax, tf32-rounded           -> d_W in place
//   k_gemm    : tf32 MMA, 2 CTAs/SM + cp.async DOUBLE-BUFFER -> d_O [i][s][h*32+e]
//   k_out     : tf32 MMA: (G .* O) @ Wo^T           -> out [s][i][64]

// ---------------- scratch ----------------
__device__ float d_mn[131072 * 64];
__device__ float d_V [8 * 8192 * 512];       // [h][t=s*32+e][j]  tf32-rounded
__device__ float d_G [131072 * 256];
__device__ float d_W [8 * 512 * 512];        // tf32-rounded softmax weights
__device__ float d_O [512 * 256 * 256];

__inline__ __device__ float warpSum(float v) {
    #pragma unroll
    for (int o = 16; o > 0; o >>= 1) v += __shfl_xor_sync(0xffffffffu, v, o);
    return v;
}
__inline__ __device__ float warpMax(float v) {
    #pragma unroll
    for (int o = 16; o > 0; o >>= 1) v = fmaxf(v, __shfl_xor_sync(0xffffffffu, v, o));
    return v;
}
__inline__ __device__ float to_tf32(float x) {
    uint32_t u;
    asm("cvt.rna.tf32.f32 %0, %1;" : "=r"(u) : "f"(x));
    return __uint_as_float(u);
}
#define MMA_TF32(acc, af, bf)                                             \
    asm volatile(                                                         \
        "mma.sync.aligned.m16n8k8.row.col.f32.tf32.tf32.f32 "             \
        "{%0,%1,%2,%3}, {%4,%5,%6,%7}, {%8,%9}, {%0,%1,%2,%3};\n"         \
        : "+f"((acc)[0]), "+f"((acc)[1]), "+f"((acc)[2]), "+f"((acc)[3])  \
        : "r"((af)[0]), "r"((af)[1]), "r"((af)[2]), "r"((af)[3]),         \
          "r"((bf)[0]), "r"((bf)[1]))
#define CP_ASYNC16(smem_u32, gptr)                                        \
    asm volatile("cp.async.cg.shared.global [%0], [%1], 16;\n"            \
                 :: "r"(smem_u32), "l"(gptr))

// ---------------- kernel 1: LayerNorm(m), tf32-rounded ----------------
__global__ void k_ln_m(const float* __restrict__ m,
                       const float* __restrict__ lw, const float* __restrict__ lb)
{
    int tid = threadIdx.x, warp = tid >> 5, lane = tid & 31;
    int r = blockIdx.x * 8 + warp;
    const float* row = m + (size_t)r * 64;
    float x0 = row[lane];
    float x1 = row[lane + 32];
    float s  = warpSum(x0 + x1);
    float ss = warpSum(x0 * x0 + x1 * x1);
    float mu  = s * (1.0f / 64.0f);
    float var = ss * (1.0f / 64.0f) - mu * mu;
    float rinv = rsqrtf(var + 1e-5f);
    d_mn[(size_t)r * 64 + lane]      = to_tf32((x0 - mu) * rinv * lw[lane]      + lb[lane]);
    d_mn[(size_t)r * 64 + lane + 32] = to_tf32((x1 - mu) * rinv * lw[lane + 32] + lb[lane + 32]);
}

// ---------------- kernel 2: V / G projection — tf32 MMA ----------------
__global__ void __launch_bounds__(256) k_mproj(const float* __restrict__ Wm,
                                               const float* __restrict__ Wg)
{
    __shared__ float As[128][36];
    __shared__ float Bs[32][136];
    int tid = threadIdx.x;
    int warp = tid >> 5, lane = tid & 31;
    int gid = lane >> 2, tig = lane & 3;
    int warp_m = warp & 1, warp_n = warp >> 1;
    int bx = blockIdx.x, by = blockIdx.y;
    bool isV = (bx < 2);

    float acc[4][4][4] = {};
    for (int kt = 0; kt < 64; kt += 32) {
        #pragma unroll
        for (int l = 0; l < 4; l++) {
            int e = tid + l * 256;
            int ar = e >> 3, ac = (e & 7) * 4;
            *(float4*)(&As[ar][ac]) =
                *(const float4*)(d_mn + (size_t)(by * 128 + ar) * 64 + kt + ac);
        }
        {
            int o_local = tid >> 1;
            int k0 = (tid & 1) * 16;
            int o_global = bx * 128 + o_local;
            const float* Wrow = isV ? (Wm + (size_t)o_global * 64)
                                    : (Wg + (size_t)(o_global - 256) * 64);
            #pragma unroll
            for (int i = 0; i < 16; i++) Bs[k0 + i][o_local] = to_tf32(Wrow[kt + k0 + i]);
        }
        __syncthreads();
        #pragma unroll
        for (int k0 = 0; k0 < 32; k0 += 8) {
            uint32_t af[4][4], bf[4][2];
            #pragma unroll
            for (int mt = 0; mt < 4; mt++) {
                int r0 = warp_m * 64 + mt * 16 + gid;
                af[mt][0] = __float_as_uint(As[r0    ][k0 + tig]);
                af[mt][1] = __float_as_uint(As[r0 + 8][k0 + tig]);
                af[mt][2] = __float_as_uint(As[r0    ][k0 + tig + 4]);
                af[mt][3] = __float_as_uint(As[r0 + 8][k0 + tig + 4]);
            }
            #pragma unroll
            for (int nt = 0; nt < 4; nt++) {
                int c = warp_n * 32 + nt * 8 + gid;
                bf[nt][0] = __float_as_uint(Bs[k0 + tig    ][c]);
                bf[nt][1] = __float_as_uint(Bs[k0 + tig + 4][c]);
            }
            #pragma unroll
            for (int mt = 0; mt < 4; mt++)
                #pragma unroll
                for (int nt = 0; nt < 4; nt++)
                    MMA_TF32(acc[mt][nt], af[mt], bf[nt]);
        }
        __syncthreads();
    }

    #pragma unroll
    for (int mt = 0; mt < 4; mt++) {
        int rA = by * 128 + warp_m * 64 + mt * 16 + gid;
        #pragma unroll
        for (int nt = 0; nt < 4; nt++) {
            int o = bx * 128 + warp_n * 32 + nt * 8 + 2 * tig;
            #pragma unroll
            for (int half = 0; half < 2; half++) {
                int r = rA + half * 8;
                int s = r >> 9, n = r & 511;
                float c0 = acc[mt][nt][2 * half], c1 = acc[mt][nt][2 * half + 1];
                if (isV) {
                    int h = o >> 5, e = o & 31;
                    size_t t = (size_t)s * 32 + e;
                    d_V[((size_t)h * 8192 + t    ) * 512 + n] = to_tf32(c0);
                    d_V[((size_t)h * 8192 + t + 1) * 512 + n] = to_tf32(c1);
                } else {
                    size_t base = (size_t)r * 256 + (o - 256);
                    *(float2*)(d_G + base) =
                        make_float2(1.0f / (1.0f + expf(-c0)), 1.0f / (1.0f + expf(-c1)));
                }
            }
        }
    }
}

// ---------------- kernel 3: z path -> logits (one warp per (i,j) row) ----------------
__global__ void k_zpath(const float* __restrict__ z, const float* __restrict__ mask,
                        const float* __restrict__ lw, const float* __restrict__ lb,
                        const float* __restrict__ Wz)
{
    __shared__ float sWz[8][128];
    __shared__ float sLw[128], sLb[128];
    int tid = threadIdx.x;
    for (int i = tid; i < 1024; i += 256) sWz[i >> 7][i & 127] = Wz[i];
    if (tid < 128) { sLw[tid] = lw[tid]; sLb[tid] = lb[tid]; }
    __syncthreads();

    int warp = tid >> 5, lane = tid & 31;
    int r = blockIdx.x * 8 + warp;
    const float4 zx = *(const float4*)(z + (size_t)r * 128 + lane * 4);

    float s  = zx.x + zx.y + zx.z + zx.w;
    float ss = zx.x*zx.x + zx.y*zx.y + zx.z*zx.z + zx.w*zx.w;
    s = warpSum(s); ss = warpSum(ss);
    float mu  = s * (1.0f / 128.0f);
    float var = ss * (1.0f / 128.0f) - mu * mu;
    float rinv = rsqrtf(var + 1e-5f);

    float4 w4 = *(const float4*)(sLw + lane * 4);
    float4 b4 = *(const float4*)(sLb + lane * 4);
    float y0 = (zx.x - mu) * rinv * w4.x + b4.x;
    float y1 = (zx.y - mu) * rinv * w4.y + b4.y;
    float y2 = (zx.z - mu) * rinv * w4.z + b4.z;
    float y3 = (zx.w - mu) * rinv * w4.w + b4.w;

    float bias = (1.0f - mask[r]) * (-1000000.0f);
    #pragma unroll
    for (int h = 0; h < 8; h++) {
        float4 wz = *(const float4*)(&sWz[h][lane * 4]);
        float p = y0*wz.x + y1*wz.y + y2*wz.z + y3*wz.w;
        p = warpSum(p);
        if (lane == 0) d_W[(size_t)h * 262144 + r] = p + bias;
    }
}

// ---------------- kernel 4: in-place softmax (tf32-rounded) ----------------
__global__ void k_softmax()
{
    int tid = threadIdx.x, warp = tid >> 5, lane = tid & 31;
    int r = blockIdx.x * 8 + warp;
    float* p = d_W + (size_t)r * 512;
    float v[16];
    float mx = -1e30f;
    #pragma unroll
    for (int u = 0; u < 16; u++) { v[u] = p[u * 32 + lane]; mx = fmaxf(mx, v[u]); }
    mx = warpMax(mx);
    float s = 0.f;
    #pragma unroll
    for (int u = 0; u < 16; u++) { v[u] = expf(v[u] - mx); s += v[u]; }
    s = warpSum(s);
    float inv = 1.0f / s;
    #pragma unroll
    for (int u = 0; u < 16; u++) p[u * 32 + lane] = to_tf32(v[u] * inv);
}

// ---------------- kernel 5: big GEMM — tf32 MMA, 2 CTAs/SM + cp.async double-buffer ----
// C[i, t] = sum_j w[h][i][j] * V[t][j].  A = d_W[h] [i][j]; B = d_V[h] [t][j].
// Dynamic smem: 2 stages x (A 128x36 + B 128x36) = 73728 B. While MMAing
// stage c, the cp.async group for stage c+1 is in flight (wait_group 1).
// 2 resident CTAs/SM additionally cover the barrier gaps.
__global__ void __launch_bounds__(256, 2) k_gemm()
{
    extern __shared__ float sm[];
    int tid = threadIdx.x;
    int warp = tid >> 5, lane = tid & 31;
    int gid = lane >> 2, tig = lane & 3;
    int warp_m = warp & 1, warp_n = warp >> 1;
    int bx = blockIdx.x, by = blockIdx.y, h = blockIdx.z;
    const float* A  = d_W + (size_t)h * 262144;    // [i][j]
    const float* Bv = d_V + (size_t)h * 4194304;   // [t][j]
    uint32_t smu = (uint32_t)__cvta_generic_to_shared(sm);

    // layout: [A0][A1][B0][B1], each 4608 floats
    float acc[4][4][4] = {};

    // per-thread load coords (same for every chunk)
    int row0 = tid >> 3, kc = (tid & 7) * 4;      // rows tid/8 + {0,32,64,96}

    // prologue: stage chunk 0 into buffer 0
    #pragma unroll
    for (int l = 0; l < 4; l++) {
        int row = row0 + l * 32;
        CP_ASYNC16(smu + (0 * 4608 + row * 36 + kc) * 4,
                   A  + (size_t)(by * 128 + row) * 512 + kc);
        CP_ASYNC16(smu + (2 * 4608 + row * 36 + kc) * 4,
                   Bv + (size_t)(bx * 128 + row) * 512 + kc);
    }
    asm volatile("cp.async.commit_group;\n");

    for (int c = 0; c < 16; c++) {
        int cur = c & 1;
        // issue next chunk into the other buffer, then wait for current
        if (c + 1 < 16) {
            int nxt = (c + 1) & 1;
            int ko = (c + 1) * 32;
            #pragma unroll
            for (int l = 0; l < 4; l++) {
                int row = row0 + l * 32;
                CP_ASYNC16(smu + (nxt * 4608 + row * 36 + kc) * 4,
                           A  + (size_t)(by * 128 + row) * 512 + ko + kc);
                CP_ASYNC16(smu + ((2 + nxt) * 4608 + row * 36 + kc) * 4,
                           Bv + (size_t)(bx * 128 + row) * 512 + ko + kc);
            }
            asm volatile("cp.async.commit_group;\n");
            asm volatile("cp.async.wait_group 1;\n" ::: "memory");
        } else {
            asm volatile("cp.async.wait_group 0;\n" ::: "memory");
        }
        __syncthreads();

        const float* Ap = sm + cur * 4608;
        const float* Bp = sm + (2 + cur) * 4608;
        #pragma unroll
        for (int k0 = 0; k0 < 32; k0 += 8) {
            uint32_t af[4][4], bf[4][2];
            #pragma unroll
            for (int mt = 0; mt < 4; mt++) {
                int r0 = warp_m * 64 + mt * 16 + gid;
                af[mt][0] = __float_as_uint(Ap[ r0      * 36 + k0 + tig]);
                af[mt][1] = __float_as_uint(Ap[(r0 + 8) * 36 + k0 + tig]);
                af[mt][2] = __float_as_uint(Ap[ r0      * 36 + k0 + tig + 4]);
                af[mt][3] = __float_as_uint(Ap[(r0 + 8) * 36 + k0 + tig + 4]);
            }
            #pragma unroll
            for (int nt = 0; nt < 4; nt++) {
                int cc = warp_n * 32 + nt * 8 + gid;
                bf[nt][0] = __float_as_uint(Bp[cc * 36 + k0 + tig]);
                bf[nt][1] = __float_as_uint(Bp[cc * 36 + k0 + tig + 4]);
            }
            #pragma unroll
            for (int mt = 0; mt < 4; mt++)
                #pragma unroll
                for (int nt = 0; nt < 4; nt++)
                    MMA_TF32(acc[mt][nt], af[mt], bf[nt]);
        }
        __syncthreads();   // all warps done with buffer `cur` before it is refilled
    }

    #pragma unroll
    for (int mt = 0; mt < 4; mt++) {
        int r0 = by * 128 + warp_m * 64 + mt * 16 + gid;
        #pragma unroll
        for (int nt = 0; nt < 4; nt++) {
            int t = bx * 128 + warp_n * 32 + nt * 8 + 2 * tig;
            int s = t >> 5, e = t & 31;
            size_t b0 = (size_t)r0 * 65536 + (size_t)s * 256 + h * 32 + e;
            size_t b1 = (size_t)(r0 + 8) * 65536 + (size_t)s * 256 + h * 32 + e;
            *(float2*)(d_O + b0) = make_float2(acc[mt][nt][0], acc[mt][nt][1]);
            *(float2*)(d_O + b1) = make_float2(acc[mt][nt][2], acc[mt][nt][3]);
        }
    }
}

// ---------------- kernel 6: gate + output projection — tf32 MMA ----------------
__global__ void __launch_bounds__(256) k_out(float* __restrict__ out,
                                             const float* __restrict__ Wo)
{
    __shared__ float As[128][36];
    __shared__ float Bs[32][72];
    int tid = threadIdx.x;
    int warp = tid >> 5, lane = tid & 31;
    int gid = lane >> 2, tig = lane & 3;
    int warp_m = warp >> 1, warp_n = warp & 1;
    int by = blockIdx.x;

    float acc[2][4][4] = {};
    for (int kt = 0; kt < 256; kt += 32) {
        #pragma unroll
        for (int l = 0; l < 4; l++) {
            int e = tid + l * 256;
            int ar = e >> 3, ac = (e & 7) * 4;
            int r = by * 128 + ar;
            int s = r >> 9, i = r & 511;
            float4 g4 = *(const float4*)(d_G + (size_t)r * 256 + kt + ac);
            float4 o4 = *(const float4*)(d_O + (size_t)i * 65536 + (size_t)s * 256 + kt + ac);
            As[ar][ac]   = to_tf32(g4.x * o4.x);
            As[ar][ac+1] = to_tf32(g4.y * o4.y);
            As[ar][ac+2] = to_tf32(g4.z * o4.z);
            As[ar][ac+3] = to_tf32(g4.w * o4.w);
        }
        {
            int cm = tid >> 2, k0 = (tid & 3) * 8;
            const float* Wrow = Wo + (size_t)cm * 256 + kt + k0;
            #pragma unroll
            for (int i = 0; i < 8; i++) Bs[k0 + i][cm] = to_tf32(Wrow[i]);
        }
        __syncthreads();
        #pragma unroll
        for (int k0 = 0; k0 < 32; k0 += 8) {
            uint32_t af[2][4], bf[4][2];
            #pragma unroll
            for (int mt = 0; mt < 2; mt++) {
                int r0 = warp_m * 32 + mt * 16 + gid;
                af[mt][0] = __float_as_uint(As[r0    ][k0 + tig]);
                af[mt][1] = __float_as_uint(As[r0 + 8][k0 + tig]);
                af[mt][2] = __float_as_uint(As[r0    ][k0 + tig + 4]);
                af[mt][3] = __float_as_uint(As[r0 + 8][k0 + tig + 4]);
            }
            #pragma unroll
            for (int nt = 0; nt < 4; nt++) {
                int c = warp_n * 32 + nt * 8 + gid;
                bf[nt][0] = __float_as_uint(Bs[k0 + tig    ][c]);
                bf[nt][1] = __float_as_uint(Bs[k0 + tig + 4][c]);
            }
            #pragma unroll
            for (int mt = 0; mt < 2; mt++)
                #pragma unroll
                for (int nt = 0; nt < 4; nt++)
                    MMA_TF32(acc[mt][nt], af[mt], bf[nt]);
        }
        __syncthreads();
    }

    #pragma unroll
    for (int mt = 0; mt < 2; mt++) {
        int r0 = by * 128 + warp_m * 32 + mt * 16 + gid;
        #pragma unroll
        for (int nt = 0; nt < 4; nt++) {
            int c = warp_n * 32 + nt * 8 + 2 * tig;
            *(float2*)(out + (size_t)r0 * 64 + c) =
                make_float2(acc[mt][nt][0], acc[mt][nt][1]);
            *(float2*)(out + (size_t)(r0 + 8) * 64 + c) =
                make_float2(acc[mt][nt][2], acc[mt][nt][3]);
        }
    }
}

extern "C" void kernel_launch(void* const* d_in, const int* in_sizes, int n_in,
                              void* d_out, int out_size)
{
    const float *m, *z, *mask, *lmw, *lmb, *lzw, *lzb, *Wm, *Wg, *Wz, *Wo;
    if (n_in > 0 && in_sizes[0] == 8388608) {           // insertion order
        m   = (const float*)d_in[0];  z   = (const float*)d_in[1];
        mask= (const float*)d_in[2];
        lmw = (const float*)d_in[3];  lmb = (const float*)d_in[4];
        lzw = (const float*)d_in[5];  lzb = (const float*)d_in[6];
        Wm  = (const float*)d_in[7];  Wg  = (const float*)d_in[8];
        Wz  = (const float*)d_in[9];  Wo  = (const float*)d_in[10];
    } else {                                            // alphabetical order
        Wg  = (const float*)d_in[0];  Wm  = (const float*)d_in[1];
        Wo  = (const float*)d_in[2];  Wz  = (const float*)d_in[3];
        lmb = (const float*)d_in[4];  lmw = (const float*)d_in[5];
        lzb = (const float*)d_in[6];  lzw = (const float*)d_in[7];
        m   = (const float*)d_in[8];  mask= (const float*)d_in[9];
        z   = (const float*)d_in[10];
    }
    float* out = (float*)d_out;

    const int GEMM_SMEM = 4 * 4608 * 4;   // 73728 bytes (2 stages x A+B)
    cudaFuncSetAttribute(k_gemm, cudaFuncAttributeMaxDynamicSharedMemorySize, GEMM_SMEM);

    k_ln_m<<<16384, 256>>>(m, lmw, lmb);
    dim3 gp(4, 1024);
    k_mproj<<<gp, 256>>>(Wm, Wg);
    k_zpath<<<32768, 256>>>(z, mask, lzw, lzb, Wz);
    k_softmax<<<512, 256>>>();
    dim3 gg(64, 4, 8);
    k_gemm<<<gg, 256, GEMM_SMEM>>>();
    k_out<<<1024, 256>>>(out, Wo);
}